// round 2
// baseline (speedup 1.0000x reference)
#include <cuda_runtime.h>

#define NP      16384
#define NTOT    (2 * NP)
#define G       64
#define C1      (G * G * G)          // 262144 cells per cloud
#define C2      (2 * C1)
#define GRID_LO (-4.8f)
#define H       0.15f
#define INV_H   (1.0f / 0.15f)

// ---------------- scratch (device globals; no allocation) ----------------
__device__ int    g_counts[C2];
__device__ int    g_cursor[C2];
__device__ int    g_starts[C2 + 1];
__device__ int    g_bsum[512];
__device__ float4 g_pts[NTOT];        // counting-sorted points, cloud0 then cloud1
__device__ float  g_min[NTOT];        // per-query min d^2 (dir0: pred->gt, dir1: gt->pred)

__device__ __forceinline__ int cellClamp(float v) {
    int c = (int)floorf((v - GRID_LO) * INV_H);
    return min(G - 1, max(0, c));
}

// 1) zero counts + cursor
__global__ void k_init() {
    int i = blockIdx.x * blockDim.x + threadIdx.x;
    if (i < C2) { g_counts[i] = 0; g_cursor[i] = 0; }
}

// 2) histogram points into cells
__global__ void k_count(const float* __restrict__ pred, const float* __restrict__ gt) {
    int i = blockIdx.x * blockDim.x + threadIdx.x;
    if (i >= NTOT) return;
    int cloud = i >> 14;
    int j = i & (NP - 1);
    const float* p = cloud ? gt : pred;
    float x = p[j * 3 + 0], y = p[j * 3 + 1], z = p[j * 3 + 2];
    int ci = (cellClamp(z) * G + cellClamp(y)) * G + cellClamp(x) + cloud * C1;
    atomicAdd(&g_counts[ci], 1);
}

// 3a) per-block (1024) exclusive scan, record block totals
__global__ void k_scan1() {
    __shared__ int sh[1024];
    int i = blockIdx.x * 1024 + threadIdx.x;
    int v = g_counts[i];
    sh[threadIdx.x] = v;
    __syncthreads();
    for (int off = 1; off < 1024; off <<= 1) {
        int t = (threadIdx.x >= off) ? sh[threadIdx.x - off] : 0;
        __syncthreads();
        sh[threadIdx.x] += t;
        __syncthreads();
    }
    g_starts[i] = sh[threadIdx.x] - v;   // exclusive
    if (threadIdx.x == 1023) g_bsum[blockIdx.x] = sh[1023];
}

// 3b) exclusive scan of the 512 block totals
__global__ void k_scan2() {
    __shared__ int sh[512];
    int v = g_bsum[threadIdx.x];
    sh[threadIdx.x] = v;
    __syncthreads();
    for (int off = 1; off < 512; off <<= 1) {
        int t = (threadIdx.x >= off) ? sh[threadIdx.x - off] : 0;
        __syncthreads();
        sh[threadIdx.x] += t;
        __syncthreads();
    }
    g_bsum[threadIdx.x] = sh[threadIdx.x] - v;
}

// 3c) add block offsets; set sentinel
__global__ void k_scan3() {
    int i = blockIdx.x * 1024 + threadIdx.x;
    g_starts[i] += g_bsum[blockIdx.x];
    if (i == 0) g_starts[C2] = NTOT;
}

// 4) scatter points into cell-contiguous order
__global__ void k_scatter(const float* __restrict__ pred, const float* __restrict__ gt) {
    int i = blockIdx.x * blockDim.x + threadIdx.x;
    if (i >= NTOT) return;
    int cloud = i >> 14;
    int j = i & (NP - 1);
    const float* p = cloud ? gt : pred;
    float x = p[j * 3 + 0], y = p[j * 3 + 1], z = p[j * 3 + 2];
    int ci = (cellClamp(z) * G + cellClamp(y)) * G + cellClamp(x) + cloud * C1;
    int pos = g_starts[ci] + atomicAdd(&g_cursor[ci], 1);
    g_pts[pos] = make_float4(x, y, z, 0.0f);
}

// 5) exact NN via expanding ring search with box-face stop bound
__global__ __launch_bounds__(128) void k_query(const float* __restrict__ pred,
                                               const float* __restrict__ gt) {
    int i = blockIdx.x * blockDim.x + threadIdx.x;
    if (i >= NTOT) return;
    int dir = i >> 14;                 // 0: pred queries vs gt refs; 1: gt vs pred
    int j = i & (NP - 1);
    const float* qp = dir ? gt : pred;
    const float qx = qp[j * 3 + 0], qy = qp[j * 3 + 1], qz = qp[j * 3 + 2];
    const int refbase = (dir ? 0 : 1) * C1;

    const int cx = cellClamp(qx), cy = cellClamp(qy), cz = cellClamp(qz);

    float best = 1e30f;

    for (int r = 0; r <= G; r++) {
        const int zlo = max(cz - r, 0), zhi = min(cz + r, G - 1);
        const int ylo = max(cy - r, 0), yhi = min(cy + r, G - 1);
        const int xlo = max(cx - r, 0), xhi = min(cx + r, G - 1);

        for (int z = zlo; z <= zhi; z++) {
            const bool zface = (z == cz - r) || (z == cz + r);
            const int zb = z * G * G + refbase;
            for (int y = ylo; y <= yhi; y++) {
                const bool face = zface || (y == cy - r) || (y == cy + r);
                const int yb = zb + y * G;
                if (face) {
                    int s = g_starts[yb + xlo];
                    int e = g_starts[yb + xhi + 1];
                    for (int k = s; k < e; k++) {
                        float4 p = g_pts[k];
                        float dx = qx - p.x, dy = qy - p.y, dz = qz - p.z;
                        float d2 = fmaf(dx, dx, fmaf(dy, dy, dz * dz));
                        best = fminf(best, d2);
                    }
                } else {
                    if (cx - r >= 0) {
                        int ci = yb + cx - r;
                        int s = g_starts[ci], e = g_starts[ci + 1];
                        for (int k = s; k < e; k++) {
                            float4 p = g_pts[k];
                            float dx = qx - p.x, dy = qy - p.y, dz = qz - p.z;
                            float d2 = fmaf(dx, dx, fmaf(dy, dy, dz * dz));
                            best = fminf(best, d2);
                        }
                    }
                    if (cx + r <= G - 1 && r > 0) {
                        int ci = yb + cx + r;
                        int s = g_starts[ci], e = g_starts[ci + 1];
                        for (int k = s; k < e; k++) {
                            float4 p = g_pts[k];
                            float dx = qx - p.x, dy = qy - p.y, dz = qz - p.z;
                            float d2 = fmaf(dx, dx, fmaf(dy, dy, dz * dz));
                            best = fminf(best, d2);
                        }
                    }
                }
            }
        }

        // stop bound: true distance from q to exterior of the scanned box.
        // Sides clipped at the grid boundary are fully covered -> +inf.
        float db = 1e30f;
        if (cx - r > 0)     db = fminf(db, qx - (GRID_LO + (float)(cx - r) * H));
        if (cx + r < G - 1) db = fminf(db, (GRID_LO + (float)(cx + r + 1) * H) - qx);
        if (cy - r > 0)     db = fminf(db, qy - (GRID_LO + (float)(cy - r) * H));
        if (cy + r < G - 1) db = fminf(db, (GRID_LO + (float)(cy + r + 1) * H) - qy);
        if (cz - r > 0)     db = fminf(db, qz - (GRID_LO + (float)(cz - r) * H));
        if (cz + r < G - 1) db = fminf(db, (GRID_LO + (float)(cz + r + 1) * H) - qz);
        if (best <= db * db) break;
    }

    g_min[i] = best;
}

// 6) weighted sum of the two means
__global__ void k_reduce(const float* __restrict__ weight, float* __restrict__ out) {
    __shared__ float s0s[512], s1s[512];
    const int t = threadIdx.x;
    float s0 = 0.0f, s1 = 0.0f;
    for (int i = t; i < NP; i += 512) {
        s0 += g_min[i];
        s1 += g_min[NP + i];
    }
    s0s[t] = s0; s1s[t] = s1;
    __syncthreads();
    for (int s = 256; s > 0; s >>= 1) {
        if (t < s) { s0s[t] += s0s[t + s]; s1s[t] += s1s[t + s]; }
        __syncthreads();
    }
    if (t == 0) {
        const float w = weight[0];
        const float inv = 1.0f / (3.0f * (float)NP);
        out[0] = w * s0s[0] * inv + (1.0f - w) * s1s[0] * inv;
    }
}

extern "C" void kernel_launch(void* const* d_in, const int* in_sizes, int n_in,
                              void* d_out, int out_size) {
    const float* pred   = (const float*)d_in[0];
    const float* gt     = (const float*)d_in[1];
    const float* weight = (const float*)d_in[2];
    float* out = (float*)d_out;
    (void)in_sizes; (void)n_in; (void)out_size;

    k_init<<<(C2 + 255) / 256, 256>>>();
    k_count<<<(NTOT + 255) / 256, 256>>>(pred, gt);
    k_scan1<<<512, 1024>>>();
    k_scan2<<<1, 512>>>();
    k_scan3<<<512, 1024>>>();
    k_scatter<<<(NTOT + 255) / 256, 256>>>(pred, gt);
    k_query<<<(NTOT + 127) / 128, 128>>>(pred, gt);
    k_reduce<<<1, 512>>>(weight, out);
}

// round 3
// speedup vs baseline: 3.8479x; 3.8479x over previous
#include <cuda_runtime.h>

#define NP      16384
#define NTOT    (2 * NP)
#define G       32
#define C1      (G * G * G)          // 32768 cells per cloud
#define C2      (2 * C1)
#define GRID_LO (-4.8f)
#define H       0.3f
#define INV_H   (1.0f / 0.3f)

// ---------------- scratch (device globals; no allocation) ----------------
__device__ int    g_counts[C2];
__device__ int    g_cursor[C2];
__device__ int    g_starts[C2 + 1];
__device__ int    g_bsum[64];
__device__ float4 g_pts[NTOT];        // counting-sorted points, cloud0 then cloud1
__device__ float  g_min[NTOT];        // per-query min d^2, sorted order

__device__ __forceinline__ int cellClamp(float v) {
    int c = (int)floorf((v - GRID_LO) * INV_H);
    return min(G - 1, max(0, c));
}

// 1) zero counts + cursor
__global__ void k_init() {
    int i = blockIdx.x * blockDim.x + threadIdx.x;
    if (i < C2) { g_counts[i] = 0; g_cursor[i] = 0; }
}

// 2) histogram points into cells
__global__ void k_count(const float* __restrict__ pred, const float* __restrict__ gt) {
    int i = blockIdx.x * blockDim.x + threadIdx.x;
    if (i >= NTOT) return;
    int cloud = i >> 14;
    int j = i & (NP - 1);
    const float* p = cloud ? gt : pred;
    float x = p[j * 3 + 0], y = p[j * 3 + 1], z = p[j * 3 + 2];
    int ci = (cellClamp(z) * G + cellClamp(y)) * G + cellClamp(x) + cloud * C1;
    atomicAdd(&g_counts[ci], 1);
}

// 3a) per-block (1024) exclusive scan, record block totals
__global__ void k_scan1() {
    __shared__ int sh[1024];
    int i = blockIdx.x * 1024 + threadIdx.x;
    int v = g_counts[i];
    sh[threadIdx.x] = v;
    __syncthreads();
    for (int off = 1; off < 1024; off <<= 1) {
        int t = (threadIdx.x >= off) ? sh[threadIdx.x - off] : 0;
        __syncthreads();
        sh[threadIdx.x] += t;
        __syncthreads();
    }
    g_starts[i] = sh[threadIdx.x] - v;   // exclusive
    if (threadIdx.x == 1023) g_bsum[blockIdx.x] = sh[1023];
}

// 3b) exclusive scan of the 64 block totals
__global__ void k_scan2() {
    __shared__ int sh[64];
    int v = g_bsum[threadIdx.x];
    sh[threadIdx.x] = v;
    __syncthreads();
    for (int off = 1; off < 64; off <<= 1) {
        int t = (threadIdx.x >= off) ? sh[threadIdx.x - off] : 0;
        __syncthreads();
        sh[threadIdx.x] += t;
        __syncthreads();
    }
    g_bsum[threadIdx.x] = sh[threadIdx.x] - v;
}

// 3c) add block offsets; set sentinel
__global__ void k_scan3() {
    int i = blockIdx.x * 1024 + threadIdx.x;
    g_starts[i] += g_bsum[blockIdx.x];
    if (i == 0) g_starts[C2] = NTOT;
}

// 4) scatter points into cell-contiguous order
__global__ void k_scatter(const float* __restrict__ pred, const float* __restrict__ gt) {
    int i = blockIdx.x * blockDim.x + threadIdx.x;
    if (i >= NTOT) return;
    int cloud = i >> 14;
    int j = i & (NP - 1);
    const float* p = cloud ? gt : pred;
    float x = p[j * 3 + 0], y = p[j * 3 + 1], z = p[j * 3 + 2];
    int ci = (cellClamp(z) * G + cellClamp(y)) * G + cellClamp(x) + cloud * C1;
    int pos = g_starts[ci] + atomicAdd(&g_cursor[ci], 1);
    g_pts[pos] = make_float4(x, y, z, 0.0f);
}

// 5) exact NN. Queries are taken from the SORTED point array so adjacent
//    lanes share cells (divergence + cache coherence fix). Fast path: fully
//    unrolled 3x3x3 neighborhood with batched row-range loads (MLP=9);
//    generic expanding-ring fallback for the rare queries that need r>=2.
__global__ __launch_bounds__(128) void k_query() {
    int i = blockIdx.x * blockDim.x + threadIdx.x;
    if (i >= NTOT) return;
    // queries 0..NP-1 are sorted cloud0 (pred) -> refs cloud1 (gt); and vice versa
    const int refbase = (i < NP) ? C1 : 0;

    const float4 q = g_pts[i];
    const float qx = q.x, qy = q.y, qz = q.z;
    const int cx = cellClamp(qx), cy = cellClamp(qy), cz = cellClamp(qz);

    const int xlo = max(cx - 1, 0), xhi = min(cx + 1, G - 1);

    // ---- ring 0+1 fast path: 9 row ranges, loads batched for MLP ----
    int rs[9], re[9];
    #pragma unroll
    for (int dz = -1; dz <= 1; dz++) {
        #pragma unroll
        for (int dy = -1; dy <= 1; dy++) {
            const int z = cz + dz, y = cy + dy;
            const int idx = (dz + 1) * 3 + (dy + 1);
            const bool ok = (z >= 0) & (z < G) & (y >= 0) & (y < G);
            const int rb = refbase + (z * G + y) * G;
            rs[idx] = ok ? g_starts[rb + xlo] : 0;
            re[idx] = ok ? g_starts[rb + xhi + 1] : 0;
        }
    }

    float best = 1e30f;
    #pragma unroll
    for (int rrow = 0; rrow < 9; rrow++) {
        for (int k = rs[rrow]; k < re[rrow]; k++) {
            const float4 p = g_pts[k];
            const float dx = qx - p.x, dy = qy - p.y, dz = qz - p.z;
            best = fminf(best, fmaf(dx, dx, fmaf(dy, dy, dz * dz)));
        }
    }

    // stop bound at r=1 (grid-clipped sides are fully covered -> +inf)
    {
        float db = 1e30f;
        if (cx - 1 > 0)     db = fminf(db, qx - (GRID_LO + (float)(cx - 1) * H));
        if (cx + 1 < G - 1) db = fminf(db, (GRID_LO + (float)(cx + 2) * H) - qx);
        if (cy - 1 > 0)     db = fminf(db, qy - (GRID_LO + (float)(cy - 1) * H));
        if (cy + 1 < G - 1) db = fminf(db, (GRID_LO + (float)(cy + 2) * H) - qy);
        if (cz - 1 > 0)     db = fminf(db, qz - (GRID_LO + (float)(cz - 1) * H));
        if (cz + 1 < G - 1) db = fminf(db, (GRID_LO + (float)(cz + 2) * H) - qz);
        if (best <= db * db) { g_min[i] = best; return; }
    }

    // ---- generic expanding rings, r >= 2 (rare) ----
    for (int r = 2; r <= G; r++) {
        const int zlo = max(cz - r, 0), zhi = min(cz + r, G - 1);
        const int ylo = max(cy - r, 0), yhi = min(cy + r, G - 1);
        const int xl  = max(cx - r, 0), xh  = min(cx + r, G - 1);

        for (int z = zlo; z <= zhi; z++) {
            const bool zface = (z == cz - r) || (z == cz + r);
            const int zb = refbase + z * G * G;
            for (int y = ylo; y <= yhi; y++) {
                const bool face = zface || (y == cy - r) || (y == cy + r);
                const int yb = zb + y * G;
                if (face) {
                    const int s = g_starts[yb + xl];
                    const int e = g_starts[yb + xh + 1];
                    for (int k = s; k < e; k++) {
                        const float4 p = g_pts[k];
                        const float dx = qx - p.x, dy = qy - p.y, dz = qz - p.z;
                        best = fminf(best, fmaf(dx, dx, fmaf(dy, dy, dz * dz)));
                    }
                } else {
                    if (cx - r >= 0) {
                        const int ci = yb + cx - r;
                        const int s = g_starts[ci], e = g_starts[ci + 1];
                        for (int k = s; k < e; k++) {
                            const float4 p = g_pts[k];
                            const float dx = qx - p.x, dy = qy - p.y, dz = qz - p.z;
                            best = fminf(best, fmaf(dx, dx, fmaf(dy, dy, dz * dz)));
                        }
                    }
                    if (cx + r <= G - 1) {
                        const int ci = yb + cx + r;
                        const int s = g_starts[ci], e = g_starts[ci + 1];
                        for (int k = s; k < e; k++) {
                            const float4 p = g_pts[k];
                            const float dx = qx - p.x, dy = qy - p.y, dz = qz - p.z;
                            best = fminf(best, fmaf(dx, dx, fmaf(dy, dy, dz * dz)));
                        }
                    }
                }
            }
        }

        float db = 1e30f;
        if (cx - r > 0)     db = fminf(db, qx - (GRID_LO + (float)(cx - r) * H));
        if (cx + r < G - 1) db = fminf(db, (GRID_LO + (float)(cx + r + 1) * H) - qx);
        if (cy - r > 0)     db = fminf(db, qy - (GRID_LO + (float)(cy - r) * H));
        if (cy + r < G - 1) db = fminf(db, (GRID_LO + (float)(cy + r + 1) * H) - qy);
        if (cz - r > 0)     db = fminf(db, qz - (GRID_LO + (float)(cz - r) * H));
        if (cz + r < G - 1) db = fminf(db, (GRID_LO + (float)(cz + r + 1) * H) - qz);
        if (best <= db * db) break;
    }

    g_min[i] = best;
}

// 6) weighted sum of the two means (queries 0..NP-1 = B2A, NP.. = A2B)
__global__ void k_reduce(const float* __restrict__ weight, float* __restrict__ out) {
    __shared__ float s0s[512], s1s[512];
    const int t = threadIdx.x;
    float s0 = 0.0f, s1 = 0.0f;
    for (int i = t; i < NP; i += 512) {
        s0 += g_min[i];
        s1 += g_min[NP + i];
    }
    s0s[t] = s0; s1s[t] = s1;
    __syncthreads();
    for (int s = 256; s > 0; s >>= 1) {
        if (t < s) { s0s[t] += s0s[t + s]; s1s[t] += s1s[t + s]; }
        __syncthreads();
    }
    if (t == 0) {
        const float w = weight[0];
        const float inv = 1.0f / (3.0f * (float)NP);
        out[0] = w * s0s[0] * inv + (1.0f - w) * s1s[0] * inv;
    }
}

extern "C" void kernel_launch(void* const* d_in, const int* in_sizes, int n_in,
                              void* d_out, int out_size) {
    const float* pred   = (const float*)d_in[0];
    const float* gt     = (const float*)d_in[1];
    const float* weight = (const float*)d_in[2];
    float* out = (float*)d_out;
    (void)in_sizes; (void)n_in; (void)out_size;

    k_init<<<(C2 + 255) / 256, 256>>>();
    k_count<<<(NTOT + 255) / 256, 256>>>(pred, gt);
    k_scan1<<<C2 / 1024, 1024>>>();
    k_scan2<<<1, 64>>>();
    k_scan3<<<C2 / 1024, 1024>>>();
    k_scatter<<<(NTOT + 255) / 256, 256>>>(pred, gt);
    k_query<<<(NTOT + 127) / 128, 128>>>();
    k_reduce<<<1, 512>>>(weight, out);
}